// round 11
// baseline (speedup 1.0000x reference)
#include <cuda_runtime.h>

#define N_RES 1024
#define C_M   256
#define C_Z   128
#define NUM_BINS 15

#define CTAS_PER_SM 5
#define GRID_CTAS   (148 * CTAS_PER_SM)              // 740
#define WARPS_CTA   8
#define NWARPS      (GRID_CTAS * WARPS_CTA)          // 5920
#define NPAIRS      (N_RES * N_RES / 2)              // 524288
#define K_MAX       ((NPAIRS + NWARPS - 1) / NWARPS) // 89

// ---------------------------------------------------------------------------
// warp sum: butterfly shuffle (sm_103a has no redux.f32)
// ---------------------------------------------------------------------------
__device__ __forceinline__ float warp_sum(float v) {
    #pragma unroll
    for (int o = 16; o; o >>= 1) v += __shfl_xor_sync(0xffffffffu, v, o);
    return v;
}

// squared bin edge t (t in [0,14]); exact vs jnp.linspace(3.25,20.75,15)**2:
// 3.25 + 1.25*t is exact in fp32, square single-rounded like the reference.
__device__ __forceinline__ float edge_sq(int t) {
    float v = fmaf(1.25f, (float)t, 3.25f);
    return v * v;
}

// Reference semantics: bin b selected iff d2 > edge²(b) && d2 < edge²(b+1)
// (strict; exact-edge equality -> no bin). sqrt guess within ±1, adjust,
// then validate with the exact strict comparisons.
__device__ __forceinline__ int find_bin(float d2) {
    float s = sqrtf(d2);
    int g = __float2int_rd((s - 3.25f) * 0.8f);
    g = min(g, 14);
    if (g >= 0) {
        float lo = edge_sq(g);
        float hi = (g == 14) ? 1e8f : edge_sq(g + 1);
        if (!(d2 > lo))      g -= 1;
        else if (!(d2 < hi)) g += 1;
    }
    if (g >= 0) {
        float lo = edge_sq(g);
        float hi = (g == 14) ? 1e8f : edge_sq(g + 1);
        if (d2 > lo && d2 < hi) return g;
    }
    return -1;
}

// ---------------------------------------------------------------------------
// ONE kernel: prologue does (a) m layernorm on the first 1024 warps,
// (b) per-warp distogram bin precompute into smem; main loop streams z.
// Add table folds ln_z_b + lin_b (+ lin_w[:,bin]) into one vector.
// ---------------------------------------------------------------------------
__global__ void __launch_bounds__(256, CTAS_PER_SM)
fused_kernel(const float* __restrict__ m,
             const float* __restrict__ ln_m_w,
             const float* __restrict__ ln_m_b,
             const float* __restrict__ z,
             const float* __restrict__ x,
             const float* __restrict__ lnw,
             const float* __restrict__ lnb,
             const float* __restrict__ linw,   // [C_Z, NUM_BINS]
             const float* __restrict__ linb,   // [C_Z]
             float* __restrict__ out_m,
             float* __restrict__ out_z) {
    __shared__ float4 sh_add[(NUM_BINS + 1) * (C_Z/4)];       // 8 KB
    __shared__ unsigned short sh_bins[WARPS_CTA][K_MAX + 1];  // ~1.4 KB

    int tid  = threadIdx.x;
    int lane = tid & 31;
    int warp = tid >> 5;
    int gwarp = blockIdx.x * WARPS_CTA + warp;

    // ---- add table: sh_add[0]=lnb+linb; sh_add[b+1]=lnb+linb+linw[:,b] ----
    for (int t = tid; t < (NUM_BINS + 1) * C_Z; t += blockDim.x) {
        int slot = t / C_Z, c = t % C_Z;
        float v = lnb[c] + linb[c];
        if (slot > 0) v += linw[c * NUM_BINS + (slot - 1)];
        ((float*)sh_add)[slot * C_Z + c] = v;
    }

    // ---- m layernorm: first 1024 warps, one row each ----
    if (gwarp < N_RES) {
        const float4* mr = (const float4*)(m + (size_t)gwarp * C_M);
        float4 a0 = mr[lane];
        float4 a1 = mr[lane + 32];

        float s = a0.x + a0.y + a0.z + a0.w + a1.x + a1.y + a1.z + a1.w;
        float q = a0.x*a0.x + a0.y*a0.y + a0.z*a0.z + a0.w*a0.w
                + a1.x*a1.x + a1.y*a1.y + a1.z*a1.z + a1.w*a1.w;
        s = warp_sum(s);
        q = warp_sum(q);
        float mu  = s * (1.0f / C_M);
        float var = fmaf(-mu, mu, q * (1.0f / C_M));
        float inv = rsqrtf(var + 1e-5f);

        float4 w0 = ((const float4*)ln_m_w)[lane];
        float4 w1 = ((const float4*)ln_m_w)[lane + 32];
        float4 b0 = ((const float4*)ln_m_b)[lane];
        float4 b1 = ((const float4*)ln_m_b)[lane + 32];

        float4 o0, o1;
        o0.x = (a0.x - mu) * inv * w0.x + b0.x;  o0.y = (a0.y - mu) * inv * w0.y + b0.y;
        o0.z = (a0.z - mu) * inv * w0.z + b0.z;  o0.w = (a0.w - mu) * inv * w0.w + b0.w;
        o1.x = (a1.x - mu) * inv * w1.x + b1.x;  o1.y = (a1.y - mu) * inv * w1.y + b1.y;
        o1.z = (a1.z - mu) * inv * w1.z + b1.z;  o1.w = (a1.w - mu) * inv * w1.w + b1.w;

        float4* orow = (float4*)(out_m + (size_t)gwarp * C_M);
        orow[lane]      = o0;
        orow[lane + 32] = o1;
    }

    // ---- per-warp bin precompute: this warp's pairs are gwarp + k*NWARPS ----
    int iters = (gwarp < NPAIRS) ? ((NPAIRS - 1 - gwarp) / NWARPS + 1) : 0;
    for (int k = lane; k < iters; k += 32) {
        int p  = gwarp + k * NWARPS;
        int i  = p >> 9;
        int j0 = (p & 511) << 1;
        float xi0 = __ldg(x + i*3 + 0), xi1 = __ldg(x + i*3 + 1), xi2 = __ldg(x + i*3 + 2);
        float dxa = xi0 - __ldg(x + j0*3 + 0);
        float dya = xi1 - __ldg(x + j0*3 + 1);
        float dza = xi2 - __ldg(x + j0*3 + 2);
        float dxb = xi0 - __ldg(x + j0*3 + 3);
        float dyb = xi1 - __ldg(x + j0*3 + 4);
        float dzb = xi2 - __ldg(x + j0*3 + 5);
        float d2a = dxa*dxa + dya*dya + dza*dza;
        float d2b = dxb*dxb + dyb*dyb + dzb*dzb;
        int s0 = find_bin(d2a) + 1;
        int s1 = find_bin(d2b) + 1;
        sh_bins[warp][k] = (unsigned short)(s0 | (s1 << 8));
    }
    __syncwarp();
    __syncthreads();   // sh_add ready for all warps

    // ---- main streaming loop: 2 z rows per iteration + register prefetch ----
    float4 w = ((const float4*)lnw)[lane];

    if (iters == 0) return;

    const float4* zp = (const float4*)(z     + ((size_t)gwarp << 8));
    float4*       op = (float4*)      (out_z + ((size_t)gwarp << 8));
    const size_t step = (size_t)NWARPS << 6;   // NWARPS*256 floats / 4

    float4 a0 = __ldcs(zp + lane);
    float4 a1 = __ldcs(zp + 32 + lane);

    for (int k = 0; k < iters; k++) {
        float4 b0, b1;
        if (k + 1 < iters) {   // prefetch next pair of rows
            const float4* nb = zp + step;
            b0 = __ldcs(nb + lane);
            b1 = __ldcs(nb + 32 + lane);
        }

        // moments (E[x], E[x^2]) -> 4 independent reductions
        float s0 = a0.x + a0.y + a0.z + a0.w;
        float q0 = a0.x*a0.x + a0.y*a0.y + a0.z*a0.z + a0.w*a0.w;
        float s1 = a1.x + a1.y + a1.z + a1.w;
        float q1 = a1.x*a1.x + a1.y*a1.y + a1.z*a1.z + a1.w*a1.w;
        s0 = warp_sum(s0); q0 = warp_sum(q0);
        s1 = warp_sum(s1); q1 = warp_sum(q1);

        float mu0  = s0 * (1.0f / C_Z);
        float var0 = fmaf(-mu0, mu0, q0 * (1.0f / C_Z));
        float inv0 = rsqrtf(var0 + 1e-5f);
        float mu1  = s1 * (1.0f / C_Z);
        float var1 = fmaf(-mu1, mu1, q1 * (1.0f / C_Z));
        float inv1 = rsqrtf(var1 + 1e-5f);

        // distogram+bias add vectors via per-warp smem bin slots
        unsigned int bins = sh_bins[warp][k];
        float4 add0 = sh_add[(bins & 0xFFu) * (C_Z/4) + lane];
        float4 add1 = sh_add[(bins >> 8)   * (C_Z/4) + lane];

        float4 o0, o1;
        o0.x = fmaf((a0.x - mu0) * inv0, w.x, add0.x);
        o0.y = fmaf((a0.y - mu0) * inv0, w.y, add0.y);
        o0.z = fmaf((a0.z - mu0) * inv0, w.z, add0.z);
        o0.w = fmaf((a0.w - mu0) * inv0, w.w, add0.w);
        o1.x = fmaf((a1.x - mu1) * inv1, w.x, add1.x);
        o1.y = fmaf((a1.y - mu1) * inv1, w.y, add1.y);
        o1.z = fmaf((a1.z - mu1) * inv1, w.z, add1.z);
        o1.w = fmaf((a1.w - mu1) * inv1, w.w, add1.w);

        __stcs(op + lane, o0);
        __stcs(op + 32 + lane, o1);

        a0 = b0; a1 = b1;
        zp += step; op += step;
    }
}

// ---------------------------------------------------------------------------
// Inputs: m, z, x, ln_m_w, ln_m_b, ln_z_w, ln_z_b, lin_w, lin_b
// Output: [m_update (1024*256) | z_update (1024*1024*128)] float32
// ---------------------------------------------------------------------------
extern "C" void kernel_launch(void* const* d_in, const int* in_sizes, int n_in,
                              void* d_out, int out_size) {
    const float* m      = (const float*)d_in[0];
    const float* z      = (const float*)d_in[1];
    const float* x      = (const float*)d_in[2];
    const float* ln_m_w = (const float*)d_in[3];
    const float* ln_m_b = (const float*)d_in[4];
    const float* ln_z_w = (const float*)d_in[5];
    const float* ln_z_b = (const float*)d_in[6];
    const float* lin_w  = (const float*)d_in[7];
    const float* lin_b  = (const float*)d_in[8];

    float* out_m = (float*)d_out;
    float* out_z = out_m + (size_t)N_RES * C_M;

    fused_kernel<<<GRID_CTAS, 256>>>(m, ln_m_w, ln_m_b, z, x,
                                     ln_z_w, ln_z_b, lin_w, lin_b,
                                     out_m, out_z);
}

// round 12
// speedup vs baseline: 1.0593x; 1.0593x over previous
#include <cuda_runtime.h>

#define N_RES 1024
#define C_M   256
#define C_Z   128
#define NUM_BINS 15

#define CTAS_PER_SM 4
#define GRID_CTAS   (148 * CTAS_PER_SM)              // 592
#define WARPS_CTA   8
#define NWARPS      (GRID_CTAS * WARPS_CTA)          // 4736
#define NPAIRS      (N_RES * N_RES / 2)              // 524288
#define K_MAX       ((NPAIRS + NWARPS - 1) / NWARPS) // 111

// ---------------------------------------------------------------------------
// warp sum: butterfly shuffle (sm_103a has no redux.f32)
// ---------------------------------------------------------------------------
__device__ __forceinline__ float warp_sum(float v) {
    #pragma unroll
    for (int o = 16; o; o >>= 1) v += __shfl_xor_sync(0xffffffffu, v, o);
    return v;
}

// squared bin edge t (t in [0,14]); exact vs jnp.linspace(3.25,20.75,15)**2:
// 3.25 + 1.25*t is exact in fp32, square single-rounded like the reference.
__device__ __forceinline__ float edge_sq(int t) {
    float v = fmaf(1.25f, (float)t, 3.25f);
    return v * v;
}

// Reference semantics: bin b selected iff d2 > edge²(b) && d2 < edge²(b+1)
// (strict; exact-edge equality -> no bin). sqrt guess within ±1, adjust,
// then validate with the exact strict comparisons.
__device__ __forceinline__ int find_bin(float d2) {
    float s = sqrtf(d2);
    int g = __float2int_rd((s - 3.25f) * 0.8f);
    g = min(g, 14);
    if (g >= 0) {
        float lo = edge_sq(g);
        float hi = (g == 14) ? 1e8f : edge_sq(g + 1);
        if (!(d2 > lo))      g -= 1;
        else if (!(d2 < hi)) g += 1;
    }
    if (g >= 0) {
        float lo = edge_sq(g);
        float hi = (g == 14) ? 1e8f : edge_sq(g + 1);
        if (d2 > lo && d2 < hi) return g;
    }
    return -1;
}

// ---------------------------------------------------------------------------
// ONE kernel: prologue does (a) m layernorm on the first 1024 warps,
// (b) per-warp distogram bin precompute into smem; main loop streams z with
// a depth-2 register prefetch pipeline (2 KB in flight per warp).
// Add table folds ln_z_b + lin_b (+ lin_w[:,bin]) into one vector.
// ---------------------------------------------------------------------------
__global__ void __launch_bounds__(256, CTAS_PER_SM)
fused_kernel(const float* __restrict__ m,
             const float* __restrict__ ln_m_w,
             const float* __restrict__ ln_m_b,
             const float* __restrict__ z,
             const float* __restrict__ x,
             const float* __restrict__ lnw,
             const float* __restrict__ lnb,
             const float* __restrict__ linw,   // [C_Z, NUM_BINS]
             const float* __restrict__ linb,   // [C_Z]
             float* __restrict__ out_m,
             float* __restrict__ out_z) {
    __shared__ float4 sh_add[(NUM_BINS + 1) * (C_Z/4)];       // 8 KB
    __shared__ unsigned short sh_bins[WARPS_CTA][K_MAX + 1];  // ~1.8 KB

    int tid  = threadIdx.x;
    int lane = tid & 31;
    int warp = tid >> 5;
    int gwarp = blockIdx.x * WARPS_CTA + warp;

    // ---- add table: sh_add[0]=lnb+linb; sh_add[b+1]=lnb+linb+linw[:,b] ----
    for (int t = tid; t < (NUM_BINS + 1) * C_Z; t += blockDim.x) {
        int slot = t / C_Z, c = t % C_Z;
        float v = lnb[c] + linb[c];
        if (slot > 0) v += linw[c * NUM_BINS + (slot - 1)];
        ((float*)sh_add)[slot * C_Z + c] = v;
    }

    // ---- m layernorm: first 1024 warps, one row each ----
    if (gwarp < N_RES) {
        const float4* mr = (const float4*)(m + (size_t)gwarp * C_M);
        float4 a0 = mr[lane];
        float4 a1 = mr[lane + 32];

        float s = a0.x + a0.y + a0.z + a0.w + a1.x + a1.y + a1.z + a1.w;
        float q = a0.x*a0.x + a0.y*a0.y + a0.z*a0.z + a0.w*a0.w
                + a1.x*a1.x + a1.y*a1.y + a1.z*a1.z + a1.w*a1.w;
        s = warp_sum(s);
        q = warp_sum(q);
        float mu  = s * (1.0f / C_M);
        float var = fmaf(-mu, mu, q * (1.0f / C_M));
        float inv = rsqrtf(var + 1e-5f);

        float4 w0 = ((const float4*)ln_m_w)[lane];
        float4 w1 = ((const float4*)ln_m_w)[lane + 32];
        float4 b0 = ((const float4*)ln_m_b)[lane];
        float4 b1 = ((const float4*)ln_m_b)[lane + 32];

        float4 o0, o1;
        o0.x = (a0.x - mu) * inv * w0.x + b0.x;  o0.y = (a0.y - mu) * inv * w0.y + b0.y;
        o0.z = (a0.z - mu) * inv * w0.z + b0.z;  o0.w = (a0.w - mu) * inv * w0.w + b0.w;
        o1.x = (a1.x - mu) * inv * w1.x + b1.x;  o1.y = (a1.y - mu) * inv * w1.y + b1.y;
        o1.z = (a1.z - mu) * inv * w1.z + b1.z;  o1.w = (a1.w - mu) * inv * w1.w + b1.w;

        float4* orow = (float4*)(out_m + (size_t)gwarp * C_M);
        orow[lane]      = o0;
        orow[lane + 32] = o1;
    }

    // ---- per-warp bin precompute: this warp's pairs are gwarp + k*NWARPS ----
    int iters = (gwarp < NPAIRS) ? ((NPAIRS - 1 - gwarp) / NWARPS + 1) : 0;
    for (int k = lane; k < iters; k += 32) {
        int p  = gwarp + k * NWARPS;
        int i  = p >> 9;
        int j0 = (p & 511) << 1;
        float xi0 = __ldg(x + i*3 + 0), xi1 = __ldg(x + i*3 + 1), xi2 = __ldg(x + i*3 + 2);
        float dxa = xi0 - __ldg(x + j0*3 + 0);
        float dya = xi1 - __ldg(x + j0*3 + 1);
        float dza = xi2 - __ldg(x + j0*3 + 2);
        float dxb = xi0 - __ldg(x + j0*3 + 3);
        float dyb = xi1 - __ldg(x + j0*3 + 4);
        float dzb = xi2 - __ldg(x + j0*3 + 5);
        float d2a = dxa*dxa + dya*dya + dza*dza;
        float d2b = dxb*dxb + dyb*dyb + dzb*dzb;
        int s0 = find_bin(d2a) + 1;
        int s1 = find_bin(d2b) + 1;
        sh_bins[warp][k] = (unsigned short)(s0 | (s1 << 8));
    }
    __syncwarp();
    __syncthreads();   // sh_add ready for all warps

    // ---- main streaming loop: 2 z rows per iteration, depth-2 prefetch ----
    float4 w = ((const float4*)lnw)[lane];

    if (iters == 0) return;

    const float4* zp = (const float4*)(z     + ((size_t)gwarp << 8));
    float4*       op = (float4*)      (out_z + ((size_t)gwarp << 8));
    const size_t step = (size_t)NWARPS << 6;   // NWARPS*256 floats / 4

    // pipeline fill: a = rows(k=0), b = rows(k=1)
    float4 a0 = __ldcs(zp + lane);
    float4 a1 = __ldcs(zp + 32 + lane);
    float4 b0, b1;
    if (iters > 1) {
        const float4* p1 = zp + step;
        b0 = __ldcs(p1 + lane);
        b1 = __ldcs(p1 + 32 + lane);
    }

    for (int k = 0; k < iters; k++) {
        float4 c0, c1;
        if (k + 2 < iters) {   // prefetch rows for k+2 (depth 2)
            const float4* p2 = zp + 2 * step;
            c0 = __ldcs(p2 + lane);
            c1 = __ldcs(p2 + 32 + lane);
        }

        // moments (E[x], E[x^2]) -> 4 independent reductions
        float s0 = a0.x + a0.y + a0.z + a0.w;
        float q0 = a0.x*a0.x + a0.y*a0.y + a0.z*a0.z + a0.w*a0.w;
        float s1 = a1.x + a1.y + a1.z + a1.w;
        float q1 = a1.x*a1.x + a1.y*a1.y + a1.z*a1.z + a1.w*a1.w;
        s0 = warp_sum(s0); q0 = warp_sum(q0);
        s1 = warp_sum(s1); q1 = warp_sum(q1);

        float mu0  = s0 * (1.0f / C_Z);
        float var0 = fmaf(-mu0, mu0, q0 * (1.0f / C_Z));
        float inv0 = rsqrtf(var0 + 1e-5f);
        float mu1  = s1 * (1.0f / C_Z);
        float var1 = fmaf(-mu1, mu1, q1 * (1.0f / C_Z));
        float inv1 = rsqrtf(var1 + 1e-5f);

        // distogram+bias add vectors via per-warp smem bin slots
        unsigned int bins = sh_bins[warp][k];
        float4 add0 = sh_add[(bins & 0xFFu) * (C_Z/4) + lane];
        float4 add1 = sh_add[(bins >> 8)   * (C_Z/4) + lane];

        float4 o0, o1;
        o0.x = fmaf((a0.x - mu0) * inv0, w.x, add0.x);
        o0.y = fmaf((a0.y - mu0) * inv0, w.y, add0.y);
        o0.z = fmaf((a0.z - mu0) * inv0, w.z, add0.z);
        o0.w = fmaf((a0.w - mu0) * inv0, w.w, add0.w);
        o1.x = fmaf((a1.x - mu1) * inv1, w.x, add1.x);
        o1.y = fmaf((a1.y - mu1) * inv1, w.y, add1.y);
        o1.z = fmaf((a1.z - mu1) * inv1, w.z, add1.z);
        o1.w = fmaf((a1.w - mu1) * inv1, w.w, add1.w);

        __stcs(op + lane, o0);
        __stcs(op + 32 + lane, o1);

        a0 = b0; a1 = b1;
        b0 = c0; b1 = c1;
        zp += step; op += step;
    }
}

// ---------------------------------------------------------------------------
// Inputs: m, z, x, ln_m_w, ln_m_b, ln_z_w, ln_z_b, lin_w, lin_b
// Output: [m_update (1024*256) | z_update (1024*1024*128)] float32
// ---------------------------------------------------------------------------
extern "C" void kernel_launch(void* const* d_in, const int* in_sizes, int n_in,
                              void* d_out, int out_size) {
    const float* m      = (const float*)d_in[0];
    const float* z      = (const float*)d_in[1];
    const float* x      = (const float*)d_in[2];
    const float* ln_m_w = (const float*)d_in[3];
    const float* ln_m_b = (const float*)d_in[4];
    const float* ln_z_w = (const float*)d_in[5];
    const float* ln_z_b = (const float*)d_in[6];
    const float* lin_w  = (const float*)d_in[7];
    const float* lin_b  = (const float*)d_in[8];

    float* out_m = (float*)d_out;
    float* out_z = out_m + (size_t)N_RES * C_M;

    fused_kernel<<<GRID_CTAS, 256>>>(m, ln_m_w, ln_m_b, z, x,
                                     ln_z_w, ln_z_b, lin_w, lin_b,
                                     out_m, out_z);
}